// round 6
// baseline (speedup 1.0000x reference)
#include <cuda_runtime.h>
#include <cuda_bf16.h>
#include <cstdint>

// CausalTrajectoryPrediction: fused 3-GEMM MLP, mma.sync m16n8k16 bf16,
// register-chained (C-frag of layer L packs directly into A-frag of L+1).
// R6: 16 rows/warp (mt=1) to cut regs -> 3 CTAs/SM; X A-frags hoisted
// (loaded once, reused for both L1 halves); B fragments via LDS.128
// (two ksteps per load). Block = (node, 128 batch rows), 8 warps.

namespace {
constexpr int kB       = 16384;
constexpr int kBT      = 128;
constexpr int kThreads = 256;
constexpr int kXS      = 72;     // X row stride in bf16 elems (144 B)

constexpr uint32_t OFF_X   = 0;          // bf16 [128][72] = 18432
constexpr uint32_t OFF_BP1 = 18432;      // uint2 [2sp][128][8] = 16384
constexpr uint32_t OFF_BP2 = 34816;      // uint2 [2br][2sp][32][8] = 8192
constexpr uint32_t OFF_BP3 = 43008;      // uint2 [2sp][64][8] = 8192
constexpr uint32_t OFF_XI  = 51200;      // float [128]
constexpr uint32_t OFF_W3X = 51712;      // float [64]
constexpr uint32_t OFF_B3A = 51968;      // float [64]
constexpr uint32_t OFF_W3B = 52224;      // float [64]
constexpr uint32_t OFF_B3B = 52480;      // float
constexpr uint32_t SMEM_BYTES = 52496;
} // namespace

__device__ __forceinline__ uint32_t smem_u32(const void* p) {
    uint32_t a;
    asm("{ .reg .u64 t; cvta.to.shared.u64 t, %1; cvt.u32.u64 %0, t; }"
        : "=r"(a) : "l"(p));
    return a;
}
__device__ __forceinline__ uint32_t bf2(float a, float b) {
    __nv_bfloat162 h = __floats2bfloat162_rn(a, b);
    return *reinterpret_cast<uint32_t*>(&h);
}
__device__ __forceinline__ void ldmat4(uint32_t r[4], uint32_t saddr) {
    asm volatile("ldmatrix.sync.aligned.m8n8.x4.shared.b16 {%0,%1,%2,%3}, [%4];"
                 : "=r"(r[0]), "=r"(r[1]), "=r"(r[2]), "=r"(r[3]) : "r"(saddr));
}
__device__ __forceinline__ void mma16(float d[4], const uint32_t a[4],
                                      uint32_t b0, uint32_t b1) {
    asm volatile(
        "mma.sync.aligned.m16n8k16.row.col.f32.bf16.bf16.f32 "
        "{%0,%1,%2,%3}, {%4,%5,%6,%7}, {%8,%9}, {%0,%1,%2,%3};"
        : "+f"(d[0]), "+f"(d[1]), "+f"(d[2]), "+f"(d[3])
        : "r"(a[0]), "r"(a[1]), "r"(a[2]), "r"(a[3]), "r"(b0), "r"(b1));
}
// relu + pack two adjacent C n-tiles (2s, 2s+1) -> A fragment for kstep s.
__device__ __forceinline__ void pack2(uint32_t a[4], const float c0[4],
                                      const float c1[4]) {
    a[0] = bf2(fmaxf(c0[0], 0.f), fmaxf(c0[1], 0.f));
    a[1] = bf2(fmaxf(c0[2], 0.f), fmaxf(c0[3], 0.f));
    a[2] = bf2(fmaxf(c1[0], 0.f), fmaxf(c1[1], 0.f));
    a[3] = bf2(fmaxf(c1[2], 0.f), fmaxf(c1[3], 0.f));
}

__global__ void __launch_bounds__(kThreads, 3)
ctp_r6_kernel(const float* __restrict__ x,
              const float* __restrict__ W1a, const float* __restrict__ W1b,
              const float* __restrict__ W2a, const float* __restrict__ W2b,
              const float* __restrict__ W3a, const float* __restrict__ b3a,
              const float* __restrict__ W3b, const float* __restrict__ b3b,
              float* __restrict__ out)
{
    extern __shared__ char smem[];
    __nv_bfloat16* Xs = reinterpret_cast<__nv_bfloat16*>(smem + OFF_X);
    uint2* bp1 = reinterpret_cast<uint2*>(smem + OFF_BP1);
    uint2* bp2 = reinterpret_cast<uint2*>(smem + OFF_BP2);
    uint2* bp3 = reinterpret_cast<uint2*>(smem + OFF_BP3);
    float* xi    = reinterpret_cast<float*>(smem + OFF_XI);
    float* w3x   = reinterpret_cast<float*>(smem + OFF_W3X);
    float* b3a_s = reinterpret_cast<float*>(smem + OFF_B3A);
    float* w3b_s = reinterpret_cast<float*>(smem + OFF_W3B);
    float* b3b_s = reinterpret_cast<float*>(smem + OFF_B3B);

    const int tid   = threadIdx.x;
    const int node  = blockIdx.y;
    const int bbase = blockIdx.x * kBT;

    // ---------------- staging ----------------
    {   // X: mask col `node`, save fp32 x[:,node]
        const float* xg = x + (size_t)bbase * 64;
        for (int idx = tid; idx < kBT * 16; idx += kThreads) {
            const int row = idx >> 4, j = idx & 15;
            float4 v = *reinterpret_cast<const float4*>(xg + row * 64 + j * 4);
            if ((node >> 2) == j) {
                float* vv = reinterpret_cast<float*>(&v);
                xi[row] = vv[node & 3];
                vv[node & 3] = 0.0f;
            }
            *reinterpret_cast<uint2*>(Xs + row * kXS + j * 4) =
                make_uint2(bf2(v.x, v.y), bf2(v.z, v.w));
        }
    }
    // frag(s, n, t4) lives at uint2 index base + ((s>>1)*NS + n)*8 + 2*t4 + (s&1)
    // -> lane reads uint4 (ksteps s, s+1) at uint4 idx sp*NS*4 + nt*32 + lane.
    {   // BP1: [W1a;W2a], n = h 0..127, NS=128
        const float* w1 = W1a + (size_t)node * 4096;
        const float* w2 = W2a + (size_t)node * 4096;
        for (int t = tid; t < 512; t += kThreads) {
            const int n = t >> 2, s = t & 3;
            const float* src = (n < 64) ? (w1 + n * 64 + s * 16)
                                        : (w2 + (n - 64) * 64 + s * 16);
            uint2* dst = bp1 + (size_t)((s >> 1) * 128 + n) * 8 + (s & 1);
            #pragma unroll
            for (int t4 = 0; t4 < 4; t4++)
                dst[2 * t4] = make_uint2(bf2(src[2 * t4],     src[2 * t4 + 1]),
                                         bf2(src[2 * t4 + 8], src[2 * t4 + 9]));
        }
    }
    {   // BP2: br0 = W1b (k = H1 cols 0..63), br1 = W2b (cols 64..127); NS=32
        for (int t = tid; t < 256; t += kThreads) {
            const int br = t >> 7, rem = t & 127, m = rem >> 2, s = rem & 3;
            const float* src = (br ? W2b : W1b) + (size_t)node * 2048 + m * 64 + s * 16;
            uint2* dst = bp2 + (size_t)br * 512
                             + (size_t)((s >> 1) * 32 + m) * 8 + (s & 1);
            #pragma unroll
            for (int t4 = 0; t4 < 4; t4++)
                dst[2 * t4] = make_uint2(bf2(src[2 * t4],     src[2 * t4 + 1]),
                                         bf2(src[2 * t4 + 8], src[2 * t4 + 9]));
        }
    }
    {   // BP3: W3a[:,0:64], n = h, NS=64
        const float* w3 = W3a + (size_t)node * 8192;
        for (int t = tid; t < 256; t += kThreads) {
            const int n = t >> 2, s = t & 3;
            const float* src = w3 + n * 128 + s * 16;
            uint2* dst = bp3 + (size_t)((s >> 1) * 64 + n) * 8 + (s & 1);
            #pragma unroll
            for (int t4 = 0; t4 < 4; t4++)
                dst[2 * t4] = make_uint2(bf2(src[2 * t4],     src[2 * t4 + 1]),
                                         bf2(src[2 * t4 + 8], src[2 * t4 + 9]));
        }
        if (tid < 64) {
            w3x[tid]   = w3[tid * 128 + 64 + node];
            b3a_s[tid] = b3a[node * 64 + tid];
            w3b_s[tid] = W3b[node * 64 + tid];
        }
        if (tid == 0) b3b_s[0] = b3b[node];
    }
    __syncthreads();

    // ---------------- per-warp register-chained MLP (16 rows) ----------------
    const int wid = tid >> 5, lane = tid & 31;
    const int tg = lane >> 2, t4 = lane & 3;
    const int r0 = wid * 16;

    const uint4* bp1q = reinterpret_cast<const uint4*>(bp1);
    const uint4* bp2q = reinterpret_cast<const uint4*>(bp2);
    const uint4* bp3q = reinterpret_cast<const uint4*>(bp3);

    // hoisted X A-fragments (one m16 tile, 4 ksteps)
    const int mat = lane >> 3, rin = lane & 7;
    const int arow = ((mat & 1) << 3) + rin;
    const int akb  = (mat >> 1) << 4;
    const uint32_t a_base = smem_u32(Xs) + (uint32_t)(r0 + arow) * 144 + akb;
    uint32_t XA[4][4];
    #pragma unroll
    for (int s = 0; s < 4; s++) ldmat4(XA[s], a_base + s * 32);

    uint32_t A3[4][4];

    // ---- L1 half + L2 branch, for br = 0,1 ----
    #pragma unroll
    for (int br = 0; br < 2; br++) {
        float accL1[8][4];
        #pragma unroll
        for (int nt = 0; nt < 8; nt++)
            #pragma unroll
            for (int i = 0; i < 4; i++) accL1[nt][i] = 0.0f;
        #pragma unroll
        for (int sp = 0; sp < 2; sp++) {
            const uint4* bs = bp1q + sp * 512 + br * 256 + lane;
            #pragma unroll
            for (int nt = 0; nt < 8; nt++) {
                const uint4 q = bs[nt * 32];
                mma16(accL1[nt], XA[2 * sp],     q.x, q.y);
                mma16(accL1[nt], XA[2 * sp + 1], q.z, q.w);
            }
        }
        uint32_t A2[4][4];
        #pragma unroll
        for (int s = 0; s < 4; s++) pack2(A2[s], accL1[2 * s], accL1[2 * s + 1]);

        float acc4[4][4];
        #pragma unroll
        for (int nt = 0; nt < 4; nt++)
            #pragma unroll
            for (int i = 0; i < 4; i++) acc4[nt][i] = 0.0f;
        #pragma unroll
        for (int sp = 0; sp < 2; sp++) {
            const uint4* bs = bp2q + br * 256 + sp * 128 + lane;
            #pragma unroll
            for (int nt = 0; nt < 4; nt++) {
                const uint4 q = bs[nt * 32];
                mma16(acc4[nt], A2[2 * sp],     q.x, q.y);
                mma16(acc4[nt], A2[2 * sp + 1], q.z, q.w);
            }
        }
        #pragma unroll
        for (int s = 0; s < 2; s++)
            pack2(A3[2 * br + s], acc4[2 * s], acc4[2 * s + 1]);
    }

    // ---- L3 (K=64, 64 outputs) ----
    float acc[8][4];
    #pragma unroll
    for (int nt = 0; nt < 8; nt++)
        #pragma unroll
        for (int i = 0; i < 4; i++) acc[nt][i] = 0.0f;
    #pragma unroll
    for (int sp = 0; sp < 2; sp++) {
        const uint4* bs = bp3q + sp * 256 + lane;
        #pragma unroll
        for (int nt = 0; nt < 8; nt++) {
            const uint4 q = bs[nt * 32];
            mma16(acc[nt], A3[2 * sp],     q.x, q.y);
            mma16(acc[nt], A3[2 * sp + 1], q.z, q.w);
        }
    }

    // ---- epilogue (fp32) ----
    const int ru = r0 + tg;
    const float xu = xi[ru], xl = xi[ru + 8];
    float s0 = 0.f, s1 = 0.f;
    #pragma unroll
    for (int nt = 0; nt < 8; nt++) {
        const int c0 = 8 * nt + 2 * t4;
        const float wx0 = w3x[c0], wx1 = w3x[c0 + 1];
        const float ba0 = b3a_s[c0], ba1 = b3a_s[c0 + 1];
        const float wb0 = w3b_s[c0], wb1 = w3b_s[c0 + 1];
        s0 += fmaxf(acc[nt][0] + xu * wx0 + ba0, 0.f) * wb0
            + fmaxf(acc[nt][1] + xu * wx1 + ba1, 0.f) * wb1;
        s1 += fmaxf(acc[nt][2] + xl * wx0 + ba0, 0.f) * wb0
            + fmaxf(acc[nt][3] + xl * wx1 + ba1, 0.f) * wb1;
    }
    const float bb = b3b_s[0];
    s0 += __shfl_xor_sync(0xffffffff, s0, 1);
    s0 += __shfl_xor_sync(0xffffffff, s0, 2);
    s1 += __shfl_xor_sync(0xffffffff, s1, 1);
    s1 += __shfl_xor_sync(0xffffffff, s1, 2);
    if (t4 == 0) {
        out[(size_t)(bbase + ru) * 64 + node]     = fmaxf(s0 + bb, 0.f);
        out[(size_t)(bbase + ru + 8) * 64 + node] = fmaxf(s1 + bb, 0.f);
    }
}

extern "C" void kernel_launch(void* const* d_in, const int* in_sizes, int n_in,
                              void* d_out, int out_size)
{
    (void)in_sizes; (void)n_in; (void)out_size;
    const float* x   = (const float*)d_in[0];
    const float* W1a = (const float*)d_in[1];
    const float* W1b = (const float*)d_in[2];
    const float* W2a = (const float*)d_in[3];
    const float* W2b = (const float*)d_in[4];
    const float* W3a = (const float*)d_in[5];
    const float* b3a = (const float*)d_in[6];
    const float* W3b = (const float*)d_in[7];
    const float* b3b = (const float*)d_in[8];
    float* out = (float*)d_out;

    cudaFuncSetAttribute(ctp_r6_kernel,
                         cudaFuncAttributeMaxDynamicSharedMemorySize,
                         (int)SMEM_BYTES);
    dim3 grid(kB / kBT, 64);   // 128 batch tiles x 64 nodes
    ctp_r6_kernel<<<grid, kThreads, SMEM_BYTES>>>(
        x, W1a, W1b, W2a, W2b, W3a, b3a, W3b, b3b, out);
}